// round 2
// baseline (speedup 1.0000x reference)
#include <cuda_runtime.h>
#include <cuda_bf16.h>

#define NB 16384
#define LL 1024

__device__ double g_acc;

__global__ void bicut_zero() { g_acc = 0.0; }

__global__ __launch_bounds__(256) void bicut_rows(
    const float4* __restrict__ out4,   // output as float4: row stride 512
    const int4*   __restrict__ lab4)   // labels (int32) as int4: row stride 256
{
    const int row = blockIdx.x;
    const int tid = threadIdx.x;
    const int j0  = tid * 4;

    // ---- load output pairs (positions j0..j0+3) and labels up-front ----
    const float4* orow = out4 + (size_t)row * 512;
    float4 a = orow[tid * 2];       // j0, j0+1 : (o0,o1,o0,o1)
    float4 b = orow[tid * 2 + 1];   // j0+2, j0+3
    int4   l = lab4[(size_t)row * 256 + tid];

    // ---- last index with o1 <= o0 (argmax tie-break: temp=1 iff o1 > o0) ----
    int tz = -1;
    if (a.y <= a.x) tz = j0;
    if (a.w <= a.z) tz = j0 + 1;
    if (b.y <= b.x) tz = j0 + 2;
    if (b.w <= b.z) tz = j0 + 3;

    __shared__ int smax[8];
    int m = tz;
    #pragma unroll
    for (int o = 16; o; o >>= 1) m = max(m, __shfl_xor_sync(0xffffffffu, m, o));
    if ((tid & 31) == 0) smax[tid >> 5] = m;
    __syncthreads();
    if (tid < 32) {
        int v = (tid < 8) ? smax[tid] : -1;
        #pragma unroll
        for (int o = 4; o; o >>= 1) v = max(v, __shfl_xor_sync(0xffffffffu, v, o));
        if (tid == 0) smax[0] = v;
    }
    __syncthreads();
    int idx = smax[0];
    if (idx < 0) idx = LL - 1;   // all-ones row: mask all ones anyway

    // ---- masked weighted sum ----
    const float INV_ALPHA = 1.0f / 0.65f;
    float o1v[4] = {a.y, a.w, b.y, b.w};
    int   lv[4]  = {l.x, l.y, l.z, l.w};

    float s = 0.0f;
    #pragma unroll
    for (int k = 0; k < 4; k++) {
        int j = j0 + k;
        if (j <= idx) {
            float jf = (float)j;
            float r = (lv[k] == 1) ? (-1.0f / __log2f(jf + 2.0f))
                                   : ((jf + 1.0f) * INV_ALPHA);
            s += o1v[k] * r;
        }
    }

    // ---- block sum, one double atomic per row ----
    #pragma unroll
    for (int o = 16; o; o >>= 1) s += __shfl_xor_sync(0xffffffffu, s, o);
    __shared__ float ssum[8];
    if ((tid & 31) == 0) ssum[tid >> 5] = s;
    __syncthreads();
    if (tid == 0) {
        float t = 0.0f;
        #pragma unroll
        for (int w = 0; w < 8; w++) t += ssum[w];
        atomicAdd(&g_acc, (double)t);
    }
}

__global__ void bicut_finalize(float* __restrict__ out) {
    out[0] = (float)(g_acc * (1.0 / (double)NB));
}

extern "C" void kernel_launch(void* const* d_in, const int* in_sizes, int n_in,
                              void* d_out, int out_size) {
    const float4* out4 = (const float4*)d_in[0];
    const int4*   lab4 = (const int4*)d_in[1];
    float* out = (float*)d_out;

    bicut_zero<<<1, 1>>>();
    bicut_rows<<<NB, 256>>>(out4, lab4);
    bicut_finalize<<<1, 1>>>(out);
}